// round 5
// baseline (speedup 1.0000x reference)
#include <cuda_runtime.h>

// Problem constants (from reference setup_inputs)
#define T_DIM 16
#define B_DIM 32
#define N_DIM 196
#define C_DIM 512
#define TB_STRIDE (B_DIM * N_DIM * C_DIM)   // elements per timestep
#define SPIKES_ELEMS ((size_t)T_DIM * B_DIM * N_DIM * C_DIM)
#define NUM_UNITS 512                        // (b, 32-c-tile) work units
#define GRID_X 296                           // 2 CTAs per SM x 148 SMs

// 512-thread blocks, TWO resident CTAs per SM. Rationale: with one 1024-thread
// CTA, every per-timestep __syncthreads gates the whole SM's memory demand on
// the slowest warp's load completion (L1tex queue skew). Two independent CTAs
// tile over each other's barrier windows, keeping DRAM demand continuous.
//
// Block = 8 c-lanes (float4 -> 32 c) x 64 n-groups. Each thread carries 4
// v-states: n = ny + 64k (k=3 valid only for ny<4; N=196=3*64+4). All of N is
// in one block -> vpool reduction stays block-local (parity double-buffered,
// ONE barrier per t). The t+1 (or next-unit t=0) prefetch load for slot k
// issues right after slot k's spike store: uniform mixed R/W stream, reads
// always outstanding across barriers and unit switches.
__global__ __launch_bounds__(512, 2)
void lif_dual_kernel(const float* __restrict__ x,
                     const float* __restrict__ decay,
                     float* __restrict__ spikes,
                     float* __restrict__ vpool) {
    const int cx   = threadIdx.x;        // 0..7   (c-lane, float4)
    const int ny   = threadIdx.y;        // 0..63  (n-group)
    const int flat = ny * 8 + cx;        // 0..511
    const int bid  = blockIdx.x;

    const float d = decay[0];
    const float inv_n = 1.0f / (float)N_DIM;
    const bool last_ok = (ny < (N_DIM - 3 * 64));   // ny < 4

    __shared__ float red[2][64][32];     // [parity][n-group][c]  (8KB)

    const int nu = (bid + GRID_X < NUM_UNITS) ? 2 : 1;

    // unit -> ctile = unit & 15 (32 c each), b = unit >> 4; n = ny + 64k
    auto unit_base = [&](int unit) -> size_t {
        return ((size_t)(unit >> 4) * N_DIM + ny) * C_DIM + (unit & 15) * 32 + cx * 4;
    };

    // Prime the pipeline for the first unit (t=0 loads).
    float4 xv[4];
    {
        const size_t b0 = unit_base(bid);
#pragma unroll
        for (int k = 0; k < 3; k++)
            xv[k] = __ldcs(reinterpret_cast<const float4*>(x + b0 + (size_t)k * 64 * C_DIM));
        if (last_ok)
            xv[3] = __ldcs(reinterpret_cast<const float4*>(x + b0 + (size_t)3 * 64 * C_DIM));
    }

#pragma unroll 1
    for (int u = 0; u < nu; u++) {
        const int unit  = bid + u * GRID_X;
        const int ctile = unit & 15;
        const int b     = unit >> 4;
        const size_t base = unit_base(unit);

        float4 v[4];
#pragma unroll
        for (int k = 0; k < 4; k++) v[k] = make_float4(0.f, 0.f, 0.f, 0.f);

#pragma unroll 1
        for (int t = 0; t < T_DIM; t++) {
            const size_t off = base + (size_t)t * TB_STRIDE;
            const int par = t & 1;
            const bool more = (t < T_DIM - 1) || (u + 1 < nu);
            const size_t noff = (t < T_DIM - 1) ? (off + (size_t)TB_STRIDE)
                                                : unit_base(bid + GRID_X);

            float4 p = make_float4(0.f, 0.f, 0.f, 0.f);
#pragma unroll
            for (int k = 0; k < 4; k++) {
                if (k == 3 && !last_ok) break;
                const size_t ko = (size_t)k * 64 * C_DIM;
                float4 vv = v[k];
                vv.x = fmaf(d, vv.x, xv[k].x);
                vv.y = fmaf(d, vv.y, xv[k].y);
                vv.z = fmaf(d, vv.z, xv[k].z);
                vv.w = fmaf(d, vv.w, xv[k].w);
                p.x += vv.x; p.y += vv.y; p.z += vv.z; p.w += vv.w;   // pre-reset
                float4 s;
                s.x = (vv.x >= 1.0f) ? 1.0f : 0.0f;
                s.y = (vv.y >= 1.0f) ? 1.0f : 0.0f;
                s.z = (vv.z >= 1.0f) ? 1.0f : 0.0f;
                s.w = (vv.w >= 1.0f) ? 1.0f : 0.0f;
                __stcs(reinterpret_cast<float4*>(spikes + off + ko), s);
                vv.x = (s.x != 0.0f) ? 0.0f : vv.x;   // hard reset
                vv.y = (s.y != 0.0f) ? 0.0f : vv.y;
                vv.z = (s.z != 0.0f) ? 0.0f : vv.z;
                vv.w = (s.w != 0.0f) ? 0.0f : vv.w;
                v[k] = vv;
                // Interleaved prefetch for this slot (next t, or next unit t=0).
                if (more)
                    xv[k] = __ldcs(reinterpret_cast<const float4*>(x + noff + ko));
            }

            // Publish partial sums (STS.128, conflict-free).
            *reinterpret_cast<float4*>(&red[par][ny][4 * cx]) = p;

            __syncthreads();

            // 32 threads reduce 64 n-group partials for the 32 c columns;
            // hidden under in-flight prefetch loads and the co-resident CTA.
            // One barrier is safe: next iteration writes the other parity
            // buffer; rewriting this one requires passing the next barrier.
            if (flat < 32) {
                float s = 0.0f;
#pragma unroll
                for (int j = 0; j < 64; j++) s += red[par][j][flat];
                vpool[((size_t)t * B_DIM + b) * C_DIM + ctile * 32 + flat] = s * inv_n;
            }
        }
        __syncthreads();   // unit boundary: red[] parity reuse + v reinit
    }
}

extern "C" void kernel_launch(void* const* d_in, const int* in_sizes, int n_in,
                              void* d_out, int out_size) {
    const float* x     = (const float*)d_in[0];
    const float* decay = (const float*)d_in[1];
    float* spikes = (float*)d_out;
    float* vpool  = (float*)d_out + SPIKES_ELEMS;

    dim3 grid(GRID_X, 1);
    dim3 block(8, 64);    // 8 c-lanes (float4) x 64 n-groups = 512 threads
    lif_dual_kernel<<<grid, block>>>(x, decay, spikes, vpool);
}

// round 6
// speedup vs baseline: 1.0047x; 1.0047x over previous
#include <cuda_runtime.h>

// Problem constants (from reference setup_inputs)
#define T_DIM 16
#define B_DIM 32
#define N_DIM 196
#define C_DIM 512
#define TB_STRIDE (B_DIM * N_DIM * C_DIM)   // elements per timestep
#define SPIKES_ELEMS ((size_t)T_DIM * B_DIM * N_DIM * C_DIM)
#define NUM_UNITS 256                        // (b, 64-c-tile) work units
#define GRID_X 148                           // one block per SM

// FINAL (R4 config — fastest measured). Block = 16 c-lanes (float4 -> 64 c)
// x 64 n-groups (1024 threads, one CTA per SM). Each thread carries 4
// v-states: n = ny + 64k (k=3 valid only for ny<4; N=196=3*64+4). All of N
// lives in one block -> vpool reduction is block-local (parity-buffered, ONE
// barrier per timestep). 128-bit loads/stores; the t+1 (or next-unit t=0)
// prefetch load for slot k issues immediately after slot k's spike store, so
// the chip sees a uniformly mixed R/W stream (minimizes DRAM turnaround) and
// reads stay outstanding across barriers and unit switches.
//
// Measured: 413MB total traffic at ~6.07 TB/s effective = memory-bound floor.
__global__ __launch_bounds__(1024, 1)
void lif_dual_kernel(const float* __restrict__ x,
                     const float* __restrict__ decay,
                     float* __restrict__ spikes,
                     float* __restrict__ vpool) {
    const int cx   = threadIdx.x;        // 0..15  (c-lane, float4)
    const int ny   = threadIdx.y;        // 0..63  (n-group)
    const int flat = ny * 16 + cx;
    const int bid  = blockIdx.x;

    const float d = decay[0];
    const float inv_n = 1.0f / (float)N_DIM;
    const bool last_ok = (ny < (N_DIM - 3 * 64));   // ny < 4

    __shared__ float red[2][64][64];     // [parity][n-group][c]

    const int nu = (bid + GRID_X < NUM_UNITS) ? 2 : 1;

    // base(unit): b = unit>>3, ctile = unit&7; this thread: n = ny + 64k
    auto unit_base = [&](int unit) -> size_t {
        return ((size_t)(unit >> 3) * N_DIM + ny) * C_DIM + (unit & 7) * 64 + cx * 4;
    };

    // Prime the pipeline for the first unit (t=0 loads).
    float4 xv[4];
    {
        const size_t b0 = unit_base(bid);
#pragma unroll
        for (int k = 0; k < 3; k++)
            xv[k] = __ldcs(reinterpret_cast<const float4*>(x + b0 + (size_t)k * 64 * C_DIM));
        if (last_ok)
            xv[3] = __ldcs(reinterpret_cast<const float4*>(x + b0 + (size_t)3 * 64 * C_DIM));
    }

#pragma unroll 1
    for (int u = 0; u < nu; u++) {
        const int unit  = bid + u * GRID_X;
        const int ctile = unit & 7;
        const int b     = unit >> 3;
        const size_t base = unit_base(unit);

        float4 v[4];
#pragma unroll
        for (int k = 0; k < 4; k++) v[k] = make_float4(0.f, 0.f, 0.f, 0.f);

#pragma unroll 1
        for (int t = 0; t < T_DIM; t++) {
            const size_t off = base + (size_t)t * TB_STRIDE;
            const int par = t & 1;
            const bool more = (t < T_DIM - 1) || (u + 1 < nu);
            const size_t noff = (t < T_DIM - 1) ? (off + (size_t)TB_STRIDE)
                                                : unit_base(bid + GRID_X);

            float4 p = make_float4(0.f, 0.f, 0.f, 0.f);
#pragma unroll
            for (int k = 0; k < 4; k++) {
                if (k == 3 && !last_ok) break;
                const size_t ko = (size_t)k * 64 * C_DIM;
                float4 vv = v[k];
                vv.x = fmaf(d, vv.x, xv[k].x);
                vv.y = fmaf(d, vv.y, xv[k].y);
                vv.z = fmaf(d, vv.z, xv[k].z);
                vv.w = fmaf(d, vv.w, xv[k].w);
                p.x += vv.x; p.y += vv.y; p.z += vv.z; p.w += vv.w;   // pre-reset
                float4 s;
                s.x = (vv.x >= 1.0f) ? 1.0f : 0.0f;
                s.y = (vv.y >= 1.0f) ? 1.0f : 0.0f;
                s.z = (vv.z >= 1.0f) ? 1.0f : 0.0f;
                s.w = (vv.w >= 1.0f) ? 1.0f : 0.0f;
                __stcs(reinterpret_cast<float4*>(spikes + off + ko), s);
                vv.x = (s.x != 0.0f) ? 0.0f : vv.x;   // hard reset
                vv.y = (s.y != 0.0f) ? 0.0f : vv.y;
                vv.z = (s.z != 0.0f) ? 0.0f : vv.z;
                vv.w = (s.w != 0.0f) ? 0.0f : vv.w;
                v[k] = vv;
                // Interleaved prefetch for this slot (next t, or next unit t=0).
                if (more)
                    xv[k] = __ldcs(reinterpret_cast<const float4*>(x + noff + ko));
            }

            // Publish partial sums (STS.128, conflict-free).
            *reinterpret_cast<float4*>(&red[par][ny][4 * cx]) = p;

            __syncthreads();

            // 64 threads reduce 64 n-group partials for 64 c columns; hidden
            // under in-flight prefetch loads. One barrier is safe: the next
            // iteration writes the other parity buffer, and rewriting this
            // one requires these reducer threads to pass the next barrier.
            if (flat < 64) {
                float s = 0.0f;
#pragma unroll
                for (int j = 0; j < 64; j++) s += red[par][j][flat];
                vpool[((size_t)t * B_DIM + b) * C_DIM + ctile * 64 + flat] = s * inv_n;
            }
        }
        __syncthreads();   // unit boundary: red[] parity reuse + v reinit
    }
}

extern "C" void kernel_launch(void* const* d_in, const int* in_sizes, int n_in,
                              void* d_out, int out_size) {
    const float* x     = (const float*)d_in[0];
    const float* decay = (const float*)d_in[1];
    float* spikes = (float*)d_out;
    float* vpool  = (float*)d_out + SPIKES_ELEMS;

    dim3 grid(GRID_X, 1);
    dim3 block(16, 64);    // 16 c-lanes (float4) x 64 n-groups = 1024 threads
    lif_dual_kernel<<<grid, block>>>(x, decay, spikes, vpool);
}